// round 5
// baseline (speedup 1.0000x reference)
#include <cuda_runtime.h>
#include <cuda_bf16.h>
#include <math.h>

// WaveletAttention: out = x * sigmoid(relu(mean(dwt2_ll(x)) @ W1^T) @ W2^T)
// x [8,256,256,256] f32 (512 MB), W1 [16,256], W2 [256,16].
//
// mean(dwt2_ll(x)) == (1/135^2) * sum_{i,j} w[i]*w[j]*x[b,c,i,j]  (linear +
// separable), w = fixed 256-weight vector from db8 dec_lo, symmetric pad.
//
// R5: persistent kernel, software-pipelined phases. Phase p interleaves
//   scale(batch p-1): L2-hit reads (ld.cs) + DRAM writes (st.cs)
//   reduce(batch p):  DRAM reads -> L2 (evict-normal)
// so the HBM read and write streams run concurrently. Grid barrier between
// phases guarantees g_yraw[p-1] is complete before scaling. L2 window stays
// ~1 batch (64 MB): x[p-1] lines die via ld.cs as x[p] lines arrive.

#define PLANE4   16384u        // float4 per 256x256 plane
#define NBC      2048
#define INV_MEAN (1.0f/(135.0f*135.0f))

#define GRID_G   888           // 6 blocks/SM * 148 SMs, all co-resident
#define NCH      4096          // 1/16-plane chunks per batch
#define KITER    5             // ceil(NCH / GRID_G)

__device__ float g_yraw[NBC];
__device__ int   g_bar_count;
__device__ int   g_bar_phase;

// pywt db8 dec_lo, 16 taps
__constant__ float c_f[16] = {
    -0.00011747678400228192f, 0.0006754494059985568f, -0.0003917403729959771f,
    -0.00487035299301066f, 0.008746094047015655f, 0.013981027917015516f,
    -0.04408825393106472f, -0.01736930100202211f, 0.128747426620186f,
    0.00047248457399797254f, -0.2840155429624281f, -0.015829105256023893f,
    0.5853546836548691f, 0.6756307362980128f, 0.3128715909144659f,
    0.05441584224308161f
};

__device__ __forceinline__ float wcontrib(int q) {
    float s = 0.f;
#pragma unroll
    for (int k = 0; k < 16; ++k) {
        int qk = q + k;
        bool ok = ((qk & 1) == 0) && (qk >= 16) && (qk <= 284);
        s += ok ? c_f[k] : 0.f;
    }
    return s;
}
__device__ __forceinline__ float weight_at(int i) {
    return wcontrib(i + 15) + wcontrib(14 - i) + wcontrib(526 - i);
}

__global__ void init_kernel() {
    int i = blockIdx.x * blockDim.x + threadIdx.x;
    if (i < NBC) g_yraw[i] = 0.f;
    if (i == 0) { g_bar_count = 0; g_bar_phase = 0; }
}

__global__ void __launch_bounds__(256, 6)
fused_kernel(const float* __restrict__ x, float* __restrict__ out,
             const float* __restrict__ W1, const float* __restrict__ W2) {
    __shared__ float sw[256];
    __shared__ float red[256];
    __shared__ float sh_h[16];

    const int t = threadIdx.x;
    const int bid = blockIdx.x;

    sw[t] = weight_at(t);
    __syncthreads();

    const int jc = (t & 63) * 4;
    const float w0 = sw[jc], w1 = sw[jc + 1], w2 = sw[jc + 2], w3 = sw[jc + 3];
    const int rb = t >> 6;

    for (int p = 0; p < 9; ++p) {
        const int bR = p;          // batch being reduced   (p < 8)
        const int bS = p - 1;      // batch being scaled    (p >= 1)

        // FC for batch bS (g_yraw[bS] complete after barrier p-1)
        if (p >= 1) {
            const int u = t >> 4, k = t & 15;
            const float* w1p = W1 + u * 256 + k * 16;
            const float* yy = g_yraw + bS * 256 + k * 16;
            float part = 0.f;
#pragma unroll
            for (int j = 0; j < 16; ++j) part += (yy[j] * INV_MEAN) * w1p[j];
            red[t] = part;
            __syncthreads();
            if (t < 16) {
                float s = 0.f;
#pragma unroll
                for (int j = 0; j < 16; ++j) s += red[t * 16 + j];
                sh_h[t] = fmaxf(s, 0.f);
            }
            __syncthreads();
        }

        // interleaved work: reduce chunk (DRAM read) + scale chunk (L2 read + DRAM write)
        for (int k = 0; k < KITER; ++k) {
            const int ch = bid + k * GRID_G;
            if (ch < NCH) {
                const int plane = ch >> 4, q = ch & 15;

                if (p < 8) {       // ---- reduce chunk of batch bR ----
                    const float4* __restrict__ pr =
                        (const float4*)x + ((size_t)(bR * 256 + plane)) * PLANE4 + q * 1024;
                    float acc = 0.f;
#pragma unroll
                    for (int it = 0; it < 4; ++it) {
                        float4 v = pr[it * 256 + t];          // evict-normal -> L2
                        float wi = sw[q * 16 + it * 4 + rb];
                        acc += wi * (w0 * v.x + w1 * v.y + w2 * v.z + w3 * v.w);
                    }
#pragma unroll
                    for (int o = 16; o; o >>= 1)
                        acc += __shfl_down_sync(0xffffffffu, acc, o);
                    if ((t & 31) == 0)
                        atomicAdd(&g_yraw[bR * 256 + plane], acc);   // RED.F32, 8/chunk
                }

                if (p >= 1) {      // ---- scale chunk of batch bS ----
                    float sv = 0.f;
                    const float* w2p = W2 + plane * 16;
#pragma unroll
                    for (int u = 0; u < 16; ++u) sv += sh_h[u] * w2p[u];
                    sv = 1.f / (1.f + expf(-sv));

                    const size_t base = ((size_t)(bS * 256 + plane)) * PLANE4 + q * 1024;
                    const float4* __restrict__ px = (const float4*)x + base;
                    float4* __restrict__ po = (float4*)out + base;
#pragma unroll
                    for (int it = 0; it < 4; ++it) {
                        float4 v = __ldcs(px + it * 256 + t); // L2 hit, evict-first
                        v.x *= sv; v.y *= sv; v.z *= sv; v.w *= sv;
                        __stcs(po + it * 256 + t, v);         // streaming store
                    }
                }
            }
        }

        // ------------------------- grid barrier (p) -------------------------
        if (t == 0) {
            __threadfence();
            if (atomicAdd(&g_bar_count, 1) == GRID_G - 1) {
                atomicExch(&g_bar_count, 0);
                __threadfence();
                atomicExch(&g_bar_phase, p + 1);
            } else {
                while (atomicAdd(&g_bar_phase, 0) <= p) __nanosleep(64);
            }
        }
        __syncthreads();
    }
}

extern "C" void kernel_launch(void* const* d_in, const int* in_sizes, int n_in,
                              void* d_out, int out_size) {
    const float* x  = (const float*)d_in[0];
    const float* W1 = (const float*)d_in[1];   // [16,256]
    const float* W2 = (const float*)d_in[2];   // [256,16]
    float* out = (float*)d_out;

    init_kernel<<<8, 256>>>();
    fused_kernel<<<GRID_G, 256>>>(x, out, W1, W2);
}